// round 8
// baseline (speedup 1.0000x reference)
#include <cuda_runtime.h>
#include <cstdint>

// Problem dims
#define B_   32
#define S_   2048
#define H_   1024
#define U_   1024
#define MTOT (B_*S_)      // 65536 GEMM rows
#define BS_TOT (B_*S_)

// GEMM tiling (Ampere-style mma.sync; toolchain targets plain sm_100: no tcgen05)
#define BM 128
#define BN 256
#define BK 32
#define NIT (H_/BK)            // 32 mainloop iterations
#define AS_STRIDE 36           // A smem row stride (floats), rows = m, k-contig
#define BT_STRIDE 36           // B smem row stride (floats), rows = n, k-contig
#define A_FLOATS (BM*AS_STRIDE)          // 4608
#define B_FLOATS (BN*BT_STRIDE)          // 9216
#define STAGE_FLOATS (A_FLOATS+B_FLOATS) // 13824
#define STAGE_BYTES (STAGE_FLOATS*4)     // 55296
#define STAGES 4
#define SMEM_MAIN_FLOATS (STAGES*STAGE_FLOATS)      // 55296 floats = 221184 B
#define SMEM_TOTAL ((SMEM_MAIN_FLOATS + 2*BN) * 4)  // + s_dp + s_v = 223232 B

#define NTILES (U_/BN)         // 4 N-tiles -> 4 score-partial slices
#define SSPLIT 32              // context-kernel S split
#define DPSPLIT 16             // dec_proj k split

// ---------------- device scratch (static device arrays are allowed) ----------------
__device__ float g_Wt[(size_t)U_*H_];        // W2 transposed: [n][k], 4MB (k-contig)
__device__ float g_dppart[DPSPLIT*B_*U_];    // dec_proj partial sums per k-split
__device__ float g_spart[NTILES*BS_TOT];     // score partials per N-tile (deterministic)
__device__ float g_attn[BS_TOT];
__device__ float g_ctxpart[SSPLIT*B_*H_];    // context partial sums per S-chunk

// ---------------- helpers ----------------
__device__ __forceinline__ void mma_tf32(float* c, const uint32_t* a, const uint32_t* b) {
    asm volatile("mma.sync.aligned.m16n8k8.row.col.f32.tf32.tf32.f32 "
        "{%0,%1,%2,%3}, {%4,%5,%6,%7}, {%8,%9}, {%0,%1,%2,%3};"
        : "+f"(c[0]), "+f"(c[1]), "+f"(c[2]), "+f"(c[3])
        : "r"(a[0]), "r"(a[1]), "r"(a[2]), "r"(a[3]), "r"(b[0]), "r"(b[1]));
}
// ldmatrix on fp32 tiles: each m8n8.b16 tile = 8 rows x 16B (4 fp32);
// output lane l <- 32-bit word (row l/4, col l%4) == tf32 mma fragment mapping.
__device__ __forceinline__ void ldsm_x4(uint32_t& r0, uint32_t& r1, uint32_t& r2, uint32_t& r3,
                                        uint32_t saddr) {
    asm volatile("ldmatrix.sync.aligned.m8n8.x4.shared.b16 {%0,%1,%2,%3}, [%4];"
        : "=r"(r0), "=r"(r1), "=r"(r2), "=r"(r3) : "r"(saddr));
}
__device__ __forceinline__ void cp_async16(uint32_t smem_addr, const void* gptr) {
    asm volatile("cp.async.cg.shared.global [%0], [%1], 16;" :: "r"(smem_addr), "l"(gptr));
}
#define CP_ASYNC_COMMIT() asm volatile("cp.async.commit_group;" ::: "memory")
#define CP_ASYNC_WAIT2()  asm volatile("cp.async.wait_group 2;" ::: "memory")
#define CP_ASYNC_WAIT0()  asm volatile("cp.async.wait_group 0;" ::: "memory")

__device__ __forceinline__ uint32_t smem_u32(const void* p) {
    uint32_t a;
    asm("{ .reg .u64 t; cvta.to.shared.u64 t, %1; cvt.u32.u64 %0, t; }" : "=r"(a) : "l"(p));
    return a;
}

// Accurate fast tanh: 1 - 2/(e^{2x}+1). ~1e-6 error, robust at large |x|.
__device__ __forceinline__ float tanh_acc(float x) {
    float ex = __expf(2.0f * x);
    return 1.0f - __fdividef(2.0f, ex + 1.0f);
}

// ---------------- W2 transpose: g_Wt[n][k] = W_a[H_+k][n] ----------------
__global__ void k_transpose(const float* __restrict__ W_a) {
    __shared__ float tile[32][33];
    int n0 = blockIdx.x * 32, k0 = blockIdx.y * 32;
    int tx = threadIdx.x, ty = threadIdx.y;
    #pragma unroll
    for (int j = 0; j < 32; j += 8)
        tile[ty + j][tx] = W_a[(size_t)(H_ + k0 + ty + j) * U_ + n0 + tx];
    __syncthreads();
    #pragma unroll
    for (int j = 0; j < 32; j += 8)
        g_Wt[(size_t)(n0 + ty + j) * H_ + k0 + tx] = tile[tx][ty + j];
}

// ---------------- dec_proj partials ----------------
// g_dppart[ks][b][u] = sum_{k in split ks} dec[b][k] * W_a[k][u]
__global__ void k_decproj(const float* __restrict__ dec, const float* __restrict__ W_a) {
    __shared__ float sdec[B_][64];
    int u  = blockIdx.x * 128 + threadIdx.x;
    int k0 = blockIdx.y * 64;
    for (int i = threadIdx.x; i < B_ * 64; i += 128) {
        int b = i >> 6, kk = i & 63;
        sdec[b][kk] = dec[b * H_ + k0 + kk];
    }
    __syncthreads();
    float acc[B_];
    #pragma unroll
    for (int b = 0; b < B_; b++) acc[b] = 0.f;
    for (int kk = 0; kk < 64; kk++) {
        float w = W_a[(size_t)(k0 + kk) * U_ + u];
        #pragma unroll
        for (int b = 0; b < B_; b++) acc[b] = fmaf(sdec[b][kk], w, acc[b]);
    }
    float* dst = &g_dppart[blockIdx.y * (B_ * U_)];
    #pragma unroll
    for (int b = 0; b < B_; b++) dst[b * U_ + u] = acc[b];
}

// ---------------- main fused GEMM + tanh + v-dot ----------------
// CTA tile 128x256, 8 warps as 2(M)x4(N), warp tile 64x64.
// Fragments via ldmatrix.x4 on fp32 tiles (A: [m][k] k-contig, B: [n][k] k-contig).
__global__ void __launch_bounds__(256, 1) k_gemm_score(
    const float* __restrict__ enc,
    const float* __restrict__ v_a, const float* __restrict__ b_a)
{
    extern __shared__ float sm[];
    const uint32_t sb = smem_u32(sm);
    const int tid = threadIdx.x;
    const int wid = tid >> 5, lane = tid & 31;
    const int wm = wid & 1, wn = wid >> 1;        // warp grid 2(M) x 4(N)
    const int tr = lane >> 2, tc = lane & 3;
    const int n0 = blockIdx.x * BN;
    const int m0 = blockIdx.y * BM;
    const int b  = m0 >> 11;                      // m0 / S_

    float* s_dp = sm + SMEM_MAIN_FLOATS;
    float* s_v  = s_dp + BN;
    for (int i = tid; i < BN; i += 256) {
        float dp = b_a[n0 + i];
        #pragma unroll
        for (int j = 0; j < DPSPLIT; j++) dp += g_dppart[j * (B_ * U_) + b * U_ + n0 + i];
        s_dp[i] = dp;
        s_v[i]  = v_a[n0 + i];
    }

    const float* gA = enc + (size_t)m0 * H_;                   // [128 rows][1024] k-contig
    const float* gB = g_Wt + (size_t)n0 * H_;                  // [n][k] k-contig

    // ldmatrix per-lane byte offsets (within a stage)
    //  A x4 tiles: (rows mb..+7, k..k+3), (mb+8..+15, k..k+3), (mb..+7, k+4..7), (mb+8..15, k+4..7)
    const uint32_t a_lane_off =
        (uint32_t)(((lane & 7) + ((lane >> 3) & 1) * 8 + wm * 64) * (AS_STRIDE * 4)
                   + ((lane >> 4) & 1) * 16);
    //  B x4 tiles: (n nb..+7, k..3), (nb..+7, k+4..7), (nb+8..15, k..3), (nb+8..15, k+4..7)
    const uint32_t b_lane_off =
        (uint32_t)(((lane & 7) + ((lane >> 4) & 1) * 8 + wn * 64) * (BT_STRIDE * 4)
                   + ((lane >> 3) & 1) * 16);

    // async loads of one BK-chunk into stage (chunk & 3)
    auto load_chunk = [&](int chunk) {
        const int st = chunk & 3;
        const uint32_t a_base = sb + (uint32_t)st * STAGE_BYTES;
        const uint32_t b_base = a_base + A_FLOATS * 4u;
        const int k0 = chunk * BK;
        #pragma unroll
        for (int j = 0; j < 4; j++) {            // A: 128 rows x 8 chunks of 16B
            int idx = j * 256 + tid;
            int r = idx >> 3, c = idx & 7;
            cp_async16(a_base + (uint32_t)(r * (AS_STRIDE * 4) + c * 16),
                       gA + (size_t)r * H_ + k0 + c * 4);
        }
        #pragma unroll
        for (int j = 0; j < 8; j++) {            // B: 256 n-rows x 8 chunks of 16B
            int idx = j * 256 + tid;
            int nr = idx >> 3, c = idx & 7;
            cp_async16(b_base + (uint32_t)(nr * (BT_STRIDE * 4) + c * 16),
                       gB + (size_t)nr * H_ + k0 + c * 4);
        }
    };

    // prologue: stages 0..2
    #pragma unroll
    for (int c = 0; c < 3; c++) { load_chunk(c); CP_ASYNC_COMMIT(); }

    float acc[4][8][4];
    #pragma unroll
    for (int mi = 0; mi < 4; mi++)
        #pragma unroll
        for (int ni = 0; ni < 8; ni++)
            #pragma unroll
            for (int r = 0; r < 4; r++) acc[mi][ni][r] = 0.f;

    #pragma unroll 1
    for (int i = 0; i < NIT; i++) {
        CP_ASYNC_WAIT2();             // chunk i resident (3 pending -> 2)
        __syncthreads();              // all warps done with iter i-1; chunk i visible
        if (i + 3 < NIT) load_chunk(i + 3);   // overwrites stage (i-1)&3: safe
        CP_ASYNC_COMMIT();            // uniform group count (may be empty)

        const uint32_t a_frag = sb + (uint32_t)(i & 3) * STAGE_BYTES + a_lane_off;
        const uint32_t b_frag = sb + (uint32_t)(i & 3) * STAGE_BYTES + A_FLOATS * 4u + b_lane_off;
        #pragma unroll
        for (int kk = 0; kk < BK; kk += 8) {
            uint32_t au[4][4], bu[8][2];
            #pragma unroll
            for (int mi = 0; mi < 4; mi++)
                ldsm_x4(au[mi][0], au[mi][1], au[mi][2], au[mi][3],
                        a_frag + (uint32_t)(mi * 16 * AS_STRIDE * 4 + kk * 4));
            #pragma unroll
            for (int j = 0; j < 4; j++)
                ldsm_x4(bu[2*j][0], bu[2*j][1], bu[2*j+1][0], bu[2*j+1][1],
                        b_frag + (uint32_t)(j * 16 * BT_STRIDE * 4 + kk * 4));
            #pragma unroll
            for (int mi = 0; mi < 4; mi++)
                #pragma unroll
                for (int ni = 0; ni < 8; ni++)
                    mma_tf32(acc[mi][ni], au[mi], bu[ni]);
        }
    }
    CP_ASYNC_WAIT0();

    // epilogue: score partial per row = sum_n v[n] * tanh(D[m][n] + dp[n])
    float (*red)[BM] = (float (*)[BM])sm;   // [4 warp_n][128 rows]; overlays stage 0 (safe)
    #pragma unroll
    for (int mi = 0; mi < 4; mi++) {
        float s0 = 0.f, s1 = 0.f;
        #pragma unroll
        for (int ni = 0; ni < 8; ni++) {
            int c0 = wn * 64 + ni * 8 + 2 * tc;
            float dp0 = s_dp[c0], dp1 = s_dp[c0 + 1];
            float v0  = s_v[c0],  v1  = s_v[c0 + 1];
            s0 = fmaf(v0, tanh_acc(acc[mi][ni][0] + dp0), s0);
            s0 = fmaf(v1, tanh_acc(acc[mi][ni][1] + dp1), s0);
            s1 = fmaf(v0, tanh_acc(acc[mi][ni][2] + dp0), s1);
            s1 = fmaf(v1, tanh_acc(acc[mi][ni][3] + dp1), s1);
        }
        s0 += __shfl_xor_sync(0xffffffffu, s0, 1);
        s0 += __shfl_xor_sync(0xffffffffu, s0, 2);
        s1 += __shfl_xor_sync(0xffffffffu, s1, 1);
        s1 += __shfl_xor_sync(0xffffffffu, s1, 2);
        if (tc == 0) {
            int r0 = wm * 64 + mi * 16 + tr;
            red[wn][r0]     = s0;
            red[wn][r0 + 8] = s1;
        }
    }
    __syncthreads();
    if (tid < BM) {
        float s = red[0][tid] + red[1][tid] + red[2][tid] + red[3][tid];
        g_spart[(size_t)blockIdx.x * BS_TOT + m0 + tid] = s;
    }
}

// ---------------- softmax over S (per batch) ----------------
__global__ void k_softmax() {
    __shared__ float red[256];
    int b = blockIdx.x, tid = threadIdx.x;
    float vals[8];
    float mx = -1e30f;
    #pragma unroll
    for (int j = 0; j < 8; j++) {
        int m = b * S_ + j * 256 + tid;
        float s = 0.f;
        #pragma unroll
        for (int t = 0; t < NTILES; t++) s += g_spart[(size_t)t * BS_TOT + m];
        vals[j] = s;
        mx = fmaxf(mx, s);
    }
    red[tid] = mx; __syncthreads();
    for (int o = 128; o > 0; o >>= 1) { if (tid < o) red[tid] = fmaxf(red[tid], red[tid + o]); __syncthreads(); }
    mx = red[0]; __syncthreads();
    float sum = 0.f;
    #pragma unroll
    for (int j = 0; j < 8; j++) { vals[j] = __expf(vals[j] - mx); sum += vals[j]; }
    red[tid] = sum; __syncthreads();
    for (int o = 128; o > 0; o >>= 1) { if (tid < o) red[tid] += red[tid + o]; __syncthreads(); }
    float inv = 1.0f / red[0];
    #pragma unroll
    for (int j = 0; j < 8; j++) g_attn[b * S_ + j * 256 + tid] = vals[j] * inv;
}

// ---------------- context partials: sum over one S-chunk, float4 per thread ----------------
// grid (B, 1, SSPLIT); block 256; each thread owns 4 h-values, loops SCHUNK s-rows.
#define SCHUNK (S_ / SSPLIT)    // 64
__global__ void k_ctxpart(const float* __restrict__ enc) {
    __shared__ float sa[SCHUNK];
    const int b  = blockIdx.x;
    const int s0 = blockIdx.z * SCHUNK;
    if (threadIdx.x < SCHUNK) sa[threadIdx.x] = g_attn[b * S_ + s0 + threadIdx.x];
    __syncthreads();
    const float4* e = (const float4*)(enc + (size_t)b * S_ * H_ + (size_t)s0 * H_) + threadIdx.x;
    float4 acc = make_float4(0.f, 0.f, 0.f, 0.f);
    #pragma unroll 8
    for (int s = 0; s < SCHUNK; s++) {
        float w = sa[s];
        float4 v = e[(size_t)s * (H_ / 4)];
        acc.x = fmaf(w, v.x, acc.x);
        acc.y = fmaf(w, v.y, acc.y);
        acc.z = fmaf(w, v.z, acc.z);
        acc.w = fmaf(w, v.w, acc.w);
    }
    float4* dst = (float4*)(g_ctxpart + (size_t)blockIdx.z * (B_ * H_) + b * H_) + threadIdx.x;
    *dst = acc;
}

// ---------------- final reduce of context partials ----------------
__global__ void k_ctxreduce(float* __restrict__ out) {
    int idx = blockIdx.x * 256 + threadIdx.x;
    float s = 0.f;
    #pragma unroll
    for (int j = 0; j < SSPLIT; j++) s += g_ctxpart[(size_t)j * (B_ * H_) + idx];
    out[idx] = s;
}

// ---------------- launch ----------------
extern "C" void kernel_launch(void* const* d_in, const int* in_sizes, int n_in,
                              void* d_out, int out_size) {
    const float* dec = (const float*)d_in[0];   // [32,1024]
    const float* enc = (const float*)d_in[1];   // [32,2048,1024]
    const float* W_a = (const float*)d_in[2];   // [2048,1024]
    const float* b_a = (const float*)d_in[3];   // [1024]
    const float* v_a = (const float*)d_in[4];   // [1024,1]
    // d_in[5] = b_v : softmax is shift-invariant -> drops out of the output
    float* out = (float*)d_out;                 // [32,1024] fp32

    cudaFuncSetAttribute(k_gemm_score, cudaFuncAttributeMaxDynamicSharedMemorySize, SMEM_TOTAL);

    k_transpose<<<dim3(U_ / 32, H_ / 32), dim3(32, 8)>>>(W_a);
    k_decproj<<<dim3(U_ / 128, DPSPLIT), 128>>>(dec, W_a);
    k_gemm_score<<<dim3(NTILES, MTOT / BM), 256, SMEM_TOTAL>>>(enc, v_a, b_a);
    k_softmax<<<B_, 256>>>();
    k_ctxpart<<<dim3(B_, 1, SSPLIT), 256>>>(enc);
    k_ctxreduce<<<(B_ * H_) / 256, 256>>>(out);
}

// round 10
// speedup vs baseline: 1.0310x; 1.0310x over previous
#include <cuda_runtime.h>
#include <cstdint>

// Problem dims
#define B_   32
#define S_   2048
#define H_   1024
#define U_   1024
#define MTOT (B_*S_)      // 65536 GEMM rows
#define BS_TOT (B_*S_)

// GEMM tiling (Ampere-style mma.sync; toolchain targets plain sm_100: no tcgen05)
#define BM 128
#define BN 256
#define BK 32
#define NIT (H_/BK)            // 32 mainloop iterations
#define AS_STRIDE 36           // A smem row stride (floats): banks (4*tr+tc) all distinct
#define BS_STRIDE 264          // B smem row stride (floats): banks (8*tc+tr) all distinct
#define A_FLOATS (BM*AS_STRIDE)          // 4608
#define B_FLOATS (BK*BS_STRIDE)          // 8448
#define STAGE_FLOATS (A_FLOATS+B_FLOATS) // 13056
#define STAGES 4
#define SMEM_MAIN_FLOATS (STAGES*STAGE_FLOATS)      // 52224 floats = 208896 B
#define SMEM_TOTAL ((SMEM_MAIN_FLOATS + 2*BN) * 4)  // + s_dp + s_v = 210944 B

#define NTILES (U_/BN)         // 4 N-tiles -> 4 score-partial slices
#define SSPLIT 32              // context-kernel S split
#define DPSPLIT 16             // dec_proj k split

// ---------------- device scratch (static device arrays are allowed) ----------------
__device__ float g_dppart[DPSPLIT*B_*U_];    // dec_proj partial sums per k-split
__device__ float g_dp[B_*U_];                // folded dec_proj + b_a
__device__ float g_spart[NTILES*BS_TOT];     // score partials per N-tile (deterministic)
__device__ float g_attn[BS_TOT];
__device__ float g_ctxpart[SSPLIT*B_*H_];    // context partial sums per S-chunk

// ---------------- helpers ----------------
// tf32 "fast path": feed raw fp32 bits; HW mma ignores the low 13 mantissa bits.
__device__ __forceinline__ uint32_t as_tf32(float x) { return __float_as_uint(x); }

__device__ __forceinline__ void mma_tf32(float* c, const uint32_t* a, const uint32_t* b) {
    asm volatile("mma.sync.aligned.m16n8k8.row.col.f32.tf32.tf32.f32 "
        "{%0,%1,%2,%3}, {%4,%5,%6,%7}, {%8,%9}, {%0,%1,%2,%3};"
        : "+f"(c[0]), "+f"(c[1]), "+f"(c[2]), "+f"(c[3])
        : "r"(a[0]), "r"(a[1]), "r"(a[2]), "r"(a[3]), "r"(b[0]), "r"(b[1]));
}
__device__ __forceinline__ void cp_async16(uint32_t smem_addr, const void* gptr) {
    asm volatile("cp.async.cg.shared.global [%0], [%1], 16;" :: "r"(smem_addr), "l"(gptr));
}
#define CP_ASYNC_COMMIT() asm volatile("cp.async.commit_group;" ::: "memory")
#define CP_ASYNC_WAIT2()  asm volatile("cp.async.wait_group 2;" ::: "memory")
#define CP_ASYNC_WAIT0()  asm volatile("cp.async.wait_group 0;" ::: "memory")

__device__ __forceinline__ uint32_t smem_u32(const void* p) {
    uint32_t a;
    asm("{ .reg .u64 t; cvta.to.shared.u64 t, %1; cvt.u32.u64 %0, t; }" : "=r"(a) : "l"(p));
    return a;
}

// Accurate fast tanh: 1 - 2/(e^{2x}+1). ~1e-6 error, robust at large |x|.
__device__ __forceinline__ float tanh_acc(float x) {
    float ex = __expf(2.0f * x);
    return 1.0f - __fdividef(2.0f, ex + 1.0f);
}

// ---------------- dec_proj partials (half the k-splits per launch) ----------------
// g_dppart[ks][b][u] = sum_{k in split ks} dec[b][k] * W_a[k][u]
__global__ void k_decproj(const float* __restrict__ dec, const float* __restrict__ W_a,
                          int ks_off) {
    __shared__ float sdec[B_][64];
    int ks = ks_off + blockIdx.y;
    int u  = blockIdx.x * 128 + threadIdx.x;
    int k0 = ks * 64;
    for (int i = threadIdx.x; i < B_ * 64; i += 128) {
        int b = i >> 6, kk = i & 63;
        sdec[b][kk] = dec[b * H_ + k0 + kk];
    }
    __syncthreads();
    float acc[B_];
    #pragma unroll
    for (int b = 0; b < B_; b++) acc[b] = 0.f;
    for (int kk = 0; kk < 64; kk++) {
        float w = W_a[(size_t)(k0 + kk) * U_ + u];
        #pragma unroll
        for (int b = 0; b < B_; b++) acc[b] = fmaf(sdec[b][kk], w, acc[b]);
    }
    float* dst = &g_dppart[ks * (B_ * U_)];
    #pragma unroll
    for (int b = 0; b < B_; b++) dst[b * U_ + u] = acc[b];
}

// ---------------- fold: g_dp[b][u] = b_a[u] + sum_ks g_dppart[ks][b][u] ----------------
// grid: (U_/256, B_)
__global__ void k_prep(const float* __restrict__ b_a) {
    int u = blockIdx.x * 256 + threadIdx.x;   // u in [0, U_)
    int b = blockIdx.y;
    float s = b_a[u];
    #pragma unroll
    for (int j = 0; j < DPSPLIT; j++) s += g_dppart[j * (B_ * U_) + b * U_ + u];
    g_dp[b * U_ + u] = s;
}

// ---------------- main fused GEMM + tanh + v-dot ----------------
// CTA tile 128x256, 8 warps as 2(M)x4(N), warp tile 64x64 (128 accums/thread).
// Grid: (NTILES=4, M_tiles=512); N on x so CTAs sharing one A tile are adjacent.
__global__ void __launch_bounds__(256, 1) k_gemm_score(
    const float* __restrict__ enc, const float* __restrict__ W_a,
    const float* __restrict__ v_a)
{
    extern __shared__ float sm[];
    const uint32_t sb = smem_u32(sm);
    const int tid = threadIdx.x;
    const int wid = tid >> 5, lane = tid & 31;
    const int wm = wid & 1, wn = wid >> 1;        // warp grid 2(M) x 4(N)
    const int tr = lane >> 2, tc = lane & 3;
    const int n0 = blockIdx.x * BN;
    const int m0 = blockIdx.y * BM;
    const int b  = m0 >> 11;                      // m0 / S_

    float* s_dp = sm + SMEM_MAIN_FLOATS;
    float* s_v  = s_dp + BN;
    for (int i = tid; i < BN; i += 256) {
        s_dp[i] = g_dp[b * U_ + n0 + i];
        s_v[i]  = v_a[n0 + i];
    }

    const float* gA = enc + (size_t)m0 * H_;                   // [128 rows][1024]
    const float* gB = W_a + (size_t)H_ * U_ + (size_t)n0;      // [k][n] n-contig

    // async loads of one BK-chunk into stage (chunk & 3)
    auto load_chunk = [&](int chunk) {
        const int st = chunk & 3;
        const uint32_t a_base = sb + (uint32_t)(st * STAGE_FLOATS) * 4u;
        const uint32_t b_base = a_base + A_FLOATS * 4u;
        const int k0 = chunk * BK;
        #pragma unroll
        for (int j = 0; j < 4; j++) {            // A: 128 rows x 8 chunks of 16B
            int idx = j * 256 + tid;
            int r = idx >> 3, c = idx & 7;
            cp_async16(a_base + (uint32_t)(r * (AS_STRIDE * 4) + c * 16),
                       gA + (size_t)r * H_ + k0 + c * 4);
        }
        #pragma unroll
        for (int j = 0; j < 8; j++) {            // B: 32 k-rows x 64 chunks of 16B
            int idx = j * 256 + tid;
            int kr = idx >> 6, c = idx & 63;
            cp_async16(b_base + (uint32_t)(kr * (BS_STRIDE * 4) + c * 16),
                       gB + (size_t)(k0 + kr) * U_ + c * 4);
        }
    };

    // prologue: stages 0..2
    #pragma unroll
    for (int c = 0; c < 3; c++) { load_chunk(c); CP_ASYNC_COMMIT(); }

    float acc[4][8][4];
    #pragma unroll
    for (int mi = 0; mi < 4; mi++)
        #pragma unroll
        for (int ni = 0; ni < 8; ni++)
            #pragma unroll
            for (int r = 0; r < 4; r++) acc[mi][ni][r] = 0.f;

    #pragma unroll 1
    for (int i = 0; i < NIT; i++) {
        CP_ASYNC_WAIT2();             // chunk i resident (3 pending -> 2)
        __syncthreads();              // all warps done with iter i-1; chunk i visible
        if (i + 3 < NIT) load_chunk(i + 3);   // overwrites stage (i-1)&3: safe
        CP_ASYNC_COMMIT();            // uniform group count (may be empty)

        const float* As = sm + (i & 3) * STAGE_FLOATS;
        const float* Bs = As + A_FLOATS;
        #pragma unroll
        for (int kk = 0; kk < BK; kk += 8) {
            uint32_t au[4][4], bu[8][2];
            #pragma unroll
            for (int mi = 0; mi < 4; mi++) {
                int r0 = (wm * 64 + mi * 16 + tr) * AS_STRIDE;
                au[mi][0] = as_tf32(As[r0 + kk + tc]);
                au[mi][1] = as_tf32(As[r0 + 8 * AS_STRIDE + kk + tc]);
                au[mi][2] = as_tf32(As[r0 + kk + tc + 4]);
                au[mi][3] = as_tf32(As[r0 + 8 * AS_STRIDE + kk + tc + 4]);
            }
            #pragma unroll
            for (int ni = 0; ni < 8; ni++) {
                int cn = wn * 64 + ni * 8 + tr;
                bu[ni][0] = as_tf32(Bs[(kk + tc) * BS_STRIDE + cn]);
                bu[ni][1] = as_tf32(Bs[(kk + tc + 4) * BS_STRIDE + cn]);
            }
            #pragma unroll
            for (int mi = 0; mi < 4; mi++)
                #pragma unroll
                for (int ni = 0; ni < 8; ni++)
                    mma_tf32(acc[mi][ni], au[mi], bu[ni]);
        }
    }
    CP_ASYNC_WAIT0();

    // epilogue: score partial per row = sum_n v[n] * tanh(D[m][n] + dp[n])
    float (*red)[BM] = (float (*)[BM])sm;   // [4 warp_n][128 rows]; overlays stage 0 (safe)
    #pragma unroll
    for (int mi = 0; mi < 4; mi++) {
        float s0 = 0.f, s1 = 0.f;
        #pragma unroll
        for (int ni = 0; ni < 8; ni++) {
            int c0 = wn * 64 + ni * 8 + 2 * tc;
            float dp0 = s_dp[c0], dp1 = s_dp[c0 + 1];
            float v0  = s_v[c0],  v1  = s_v[c0 + 1];
            s0 = fmaf(v0, tanh_acc(acc[mi][ni][0] + dp0), s0);
            s0 = fmaf(v1, tanh_acc(acc[mi][ni][1] + dp1), s0);
            s1 = fmaf(v0, tanh_acc(acc[mi][ni][2] + dp0), s1);
            s1 = fmaf(v1, tanh_acc(acc[mi][ni][3] + dp1), s1);
        }
        s0 += __shfl_xor_sync(0xffffffffu, s0, 1);
        s0 += __shfl_xor_sync(0xffffffffu, s0, 2);
        s1 += __shfl_xor_sync(0xffffffffu, s1, 1);
        s1 += __shfl_xor_sync(0xffffffffu, s1, 2);
        if (tc == 0) {
            int r0 = wm * 64 + mi * 16 + tr;
            red[wn][r0]     = s0;
            red[wn][r0 + 8] = s1;
        }
    }
    __syncthreads();
    if (tid < BM) {
        float s = red[0][tid] + red[1][tid] + red[2][tid] + red[3][tid];
        g_spart[(size_t)blockIdx.x * BS_TOT + m0 + tid] = s;
    }
}

// ---------------- softmax over S (per batch) ----------------
__global__ void k_softmax() {
    __shared__ float red[256];
    int b = blockIdx.x, tid = threadIdx.x;
    float vals[8];
    float mx = -1e30f;
    #pragma unroll
    for (int j = 0; j < 8; j++) {
        int m = b * S_ + j * 256 + tid;
        float s = 0.f;
        #pragma unroll
        for (int t = 0; t < NTILES; t++) s += g_spart[(size_t)t * BS_TOT + m];
        vals[j] = s;
        mx = fmaxf(mx, s);
    }
    red[tid] = mx; __syncthreads();
    for (int o = 128; o > 0; o >>= 1) { if (tid < o) red[tid] = fmaxf(red[tid], red[tid + o]); __syncthreads(); }
    mx = red[0]; __syncthreads();
    float sum = 0.f;
    #pragma unroll
    for (int j = 0; j < 8; j++) { vals[j] = __expf(vals[j] - mx); sum += vals[j]; }
    red[tid] = sum; __syncthreads();
    for (int o = 128; o > 0; o >>= 1) { if (tid < o) red[tid] += red[tid + o]; __syncthreads(); }
    float inv = 1.0f / red[0];
    #pragma unroll
    for (int j = 0; j < 8; j++) g_attn[b * S_ + j * 256 + tid] = vals[j] * inv;
}

// ---------------- context partials: sum over one S-chunk, float4 per thread ----------------
// grid (B, 1, SSPLIT); block 256; each thread owns 4 h-values, loops SCHUNK s-rows.
#define SCHUNK (S_ / SSPLIT)    // 64
__global__ void k_ctxpart(const float* __restrict__ enc) {
    __shared__ float sa[SCHUNK];
    const int b  = blockIdx.x;
    const int s0 = blockIdx.z * SCHUNK;
    if (threadIdx.x < SCHUNK) sa[threadIdx.x] = g_attn[b * S_ + s0 + threadIdx.x];
    __syncthreads();
    const float4* e = (const float4*)(enc + (size_t)b * S_ * H_ + (size_t)s0 * H_) + threadIdx.x;
    float4 acc = make_float4(0.f, 0.f, 0.f, 0.f);
    #pragma unroll 8
    for (int s = 0; s < SCHUNK; s++) {
        float w = sa[s];
        float4 v = e[(size_t)s * (H_ / 4)];
        acc.x = fmaf(w, v.x, acc.x);
        acc.y = fmaf(w, v.y, acc.y);
        acc.z = fmaf(w, v.z, acc.z);
        acc.w = fmaf(w, v.w, acc.w);
    }
    float4* dst = (float4*)(g_ctxpart + (size_t)blockIdx.z * (B_ * H_) + b * H_) + threadIdx.x;
    *dst = acc;
}

// ---------------- final reduce of context partials ----------------
__global__ void k_ctxreduce(float* __restrict__ out) {
    int idx = blockIdx.x * 256 + threadIdx.x;
    float s = 0.f;
    #pragma unroll
    for (int j = 0; j < SSPLIT; j++) s += g_ctxpart[(size_t)j * (B_ * H_) + idx];
    out[idx] = s;
}

// ---------------- launch ----------------
extern "C" void kernel_launch(void* const* d_in, const int* in_sizes, int n_in,
                              void* d_out, int out_size) {
    const float* dec = (const float*)d_in[0];   // [32,1024]
    const float* enc = (const float*)d_in[1];   // [32,2048,1024]
    const float* W_a = (const float*)d_in[2];   // [2048,1024]
    const float* b_a = (const float*)d_in[3];   // [1024]
    const float* v_a = (const float*)d_in[4];   // [1024,1]
    // d_in[5] = b_v : softmax is shift-invariant -> drops out of the output
    float* out = (float*)d_out;                 // [32,1024] fp32

    cudaFuncSetAttribute(k_gemm_score, cudaFuncAttributeMaxDynamicSharedMemorySize, SMEM_TOTAL);

    // Launch order arranged so k_gemm_score is the 4th launch (ncu profiles the 4th).
    k_decproj<<<dim3(U_ / 128, DPSPLIT / 2), 128>>>(dec, W_a, 0);
    k_decproj<<<dim3(U_ / 128, DPSPLIT / 2), 128>>>(dec, W_a, DPSPLIT / 2);
    k_prep<<<dim3(U_ / 256, B_), 256>>>(b_a);
    k_gemm_score<<<dim3(NTILES, MTOT / BM), 256, SMEM_TOTAL>>>(enc, W_a, v_a);
    k_softmax<<<B_, 256>>>();
    k_ctxpart<<<dim3(B_, 1, SSPLIT), 256>>>(enc);
    k_ctxreduce<<<(B_ * H_) / 256, 256>>>(out);
}